// round 2
// baseline (speedup 1.0000x reference)
#include <cuda_runtime.h>

// Problem shape (fixed by the dataset): B=16384, D=256, C=2000.
// loss = sum_{b, c != label[b]} max(1 + (pred@sig)[b,c] - gt[b], 0)
// gt[b] = (pred@sig)[b, label[b]]  (train_classes == arange(C))

#define BM 128
#define BN 128
#define BK 8
#define TM 8
#define TN 8

#define MAX_B 16384
#define MAX_PARTIALS 4096

__device__ float g_gt[MAX_B];
__device__ float g_partials[MAX_PARTIALS];

// --- gt[b] = dot(pred[b,:], sig[:, label[b]]) -------------------------------
__global__ void gt_kernel(const float* __restrict__ pred,
                          const float* __restrict__ sig,
                          const int* __restrict__ label,
                          int D, int C) {
    int b = blockIdx.x;
    int d = threadIdx.x;               // blockDim.x == D == 256
    int lab = label[b];
    float v = pred[b * D + d] * sig[d * C + lab];
    #pragma unroll
    for (int o = 16; o > 0; o >>= 1)
        v += __shfl_down_sync(0xffffffffu, v, o);
    __shared__ float s[8];
    if ((d & 31) == 0) s[d >> 5] = v;
    __syncthreads();
    if (d == 0) {
        float t = 0.f;
        #pragma unroll
        for (int i = 0; i < 8; i++) t += s[i];
        g_gt[b] = t;
    }
}

// --- fused SGEMM + hinge epilogue -------------------------------------------
__global__ __launch_bounds__(256, 2)
void gemm_hinge_kernel(const float* __restrict__ A,   // [B, D] row-major
                       const float* __restrict__ Bm,  // [D, C] row-major
                       const int* __restrict__ label,
                       int D, int C) {
    __shared__ float As[BK][BM];      // transposed A tile
    __shared__ float Bs[BK][BN];

    const int tid = threadIdx.x;
    const int tx = tid & 15;          // 16 cols of threads
    const int ty = tid >> 4;          // 16 rows of threads
    const int rowBase = blockIdx.y * BM;
    const int colBase = blockIdx.x * BN;

    // A-tile load mapping: 128 rows x 8 k, float4 per thread (2 threads/row)
    const int aRow  = tid >> 1;
    const int aCol4 = (tid & 1) * 4;
    // B-tile load mapping: 8 k-rows x 128 cols, float4 per thread
    const int bRow  = tid >> 5;
    const int bCol4 = (tid & 31) * 4;

    float acc[TM][TN];
    #pragma unroll
    for (int i = 0; i < TM; i++)
        #pragma unroll
        for (int j = 0; j < TN; j++) acc[i][j] = 0.f;

    for (int k0 = 0; k0 < D; k0 += BK) {
        // load A (D=256 divisible by 4, rows always valid: B % BM == 0)
        float4 av = *reinterpret_cast<const float4*>(
            A + (size_t)(rowBase + aRow) * D + k0 + aCol4);
        As[aCol4 + 0][aRow] = av.x;
        As[aCol4 + 1][aRow] = av.y;
        As[aCol4 + 2][aRow] = av.z;
        As[aCol4 + 3][aRow] = av.w;

        // load B (guard the C=2000 tail)
        int gcol = colBase + bCol4;
        const float* bp = Bm + (size_t)(k0 + bRow) * C + gcol;
        if (gcol + 3 < C) {
            float4 bv = *reinterpret_cast<const float4*>(bp);
            Bs[bRow][bCol4 + 0] = bv.x;
            Bs[bRow][bCol4 + 1] = bv.y;
            Bs[bRow][bCol4 + 2] = bv.z;
            Bs[bRow][bCol4 + 3] = bv.w;
        } else {
            #pragma unroll
            for (int j = 0; j < 4; j++)
                Bs[bRow][bCol4 + j] = (gcol + j < C) ? bp[j] : 0.f;
        }
        __syncthreads();

        #pragma unroll
        for (int k = 0; k < BK; k++) {
            float ra[TM], rb[TN];
            #pragma unroll
            for (int i = 0; i < TM; i++) ra[i] = As[k][ty * TM + i];
            #pragma unroll
            for (int j = 0; j < TN; j++) rb[j] = Bs[k][tx * TN + j];
            #pragma unroll
            for (int i = 0; i < TM; i++)
                #pragma unroll
                for (int j = 0; j < TN; j++)
                    acc[i][j] = fmaf(ra[i], rb[j], acc[i][j]);
        }
        __syncthreads();
    }

    // hinge epilogue + thread-local sum
    float lsum = 0.f;
    #pragma unroll
    for (int i = 0; i < TM; i++) {
        int r = rowBase + ty * TM + i;
        float gtv = g_gt[r];
        int lab = label[r];
        #pragma unroll
        for (int j = 0; j < TN; j++) {
            int c = colBase + tx * TN + j;
            if (c < C && c != lab)
                lsum += fmaxf(1.0f + acc[i][j] - gtv, 0.f);
        }
    }

    // block reduction (deterministic tree)
    __shared__ float red[256];
    red[tid] = lsum;
    __syncthreads();
    #pragma unroll
    for (int st = 128; st > 0; st >>= 1) {
        if (tid < st) red[tid] += red[tid + st];
        __syncthreads();
    }
    if (tid == 0)
        g_partials[blockIdx.y * gridDim.x + blockIdx.x] = red[0];
}

// --- deterministic final reduction ------------------------------------------
__global__ void final_reduce_kernel(float* __restrict__ out, int n) {
    __shared__ float s[256];
    float v = 0.f;
    for (int i = threadIdx.x; i < n; i += 256) v += g_partials[i];
    s[threadIdx.x] = v;
    __syncthreads();
    #pragma unroll
    for (int st = 128; st > 0; st >>= 1) {
        if (threadIdx.x < st) s[threadIdx.x] += s[threadIdx.x + st];
        __syncthreads();
    }
    if (threadIdx.x == 0) out[0] = s[0];
}

extern "C" void kernel_launch(void* const* d_in, const int* in_sizes, int n_in,
                              void* d_out, int out_size) {
    const float* pred  = (const float*)d_in[0];   // [B, D] fp32
    const int*   label = (const int*)d_in[1];     // [B] int32
    // d_in[2]: train_classes == arange(C), unused
    const float* sig   = (const float*)d_in[3];   // [D, C] fp32

    const int Bsz = in_sizes[1];                  // 16384
    const int C   = in_sizes[2];                  // 2000
    const int D   = in_sizes[0] / Bsz;            // 256

    gt_kernel<<<Bsz, D>>>(pred, sig, label, D, C);

    dim3 grid((C + BN - 1) / BN, Bsz / BM);       // 16 x 128 = 2048 blocks
    gemm_hinge_kernel<<<grid, 256>>>(pred, sig, label, D, C);

    final_reduce_kernel<<<1, 256>>>((float*)d_out, grid.x * grid.y);
}

// round 5
// speedup vs baseline: 7.0222x; 7.0222x over previous
#include <cuda_runtime.h>
#include <cuda_bf16.h>
#include <cstdint>

// Shapes fixed by dataset: B=16384, D=256, C=2000.
// loss = sum_{b, c != label[b]} max(1 + (pred@sig)[b,c] - gt[b], 0)
// gt[b] = dot(pred[b,:], sig[:,label[b]])   (train_classes == arange(C))

#define B_SZ 16384
#define D_SZ 256
#define C_SZ 2000
#define C_PAD 2048

// -------- device scratch (no allocs allowed) --------
__device__ __nv_bfloat16 g_predb[B_SZ * D_SZ];   // [B, D]  bf16, K-major (A operand)
__device__ __nv_bfloat16 g_sigT[C_PAD * D_SZ];   // [C_pad, D] bf16, K-major (B operand [N,K])
__device__ float g_gt[B_SZ];
__device__ float g_partials[2048];

__device__ __forceinline__ uint32_t smem_u32(const void* p) {
    uint32_t a;
    asm("{ .reg .u64 t; cvta.to.shared.u64 t, %1; cvt.u32.u64 %0, t; }" : "=r"(a) : "l"(p));
    return a;
}

#define CP_ASYNC16(sm, gm) \
    asm volatile("cp.async.cg.shared.global [%0], [%1], 16;" :: "r"(sm), "l"(gm))
#define CP_COMMIT() asm volatile("cp.async.commit_group;")
#define CP_WAIT1()  asm volatile("cp.async.wait_group 1;" ::: "memory")

#define LDSM_X4(r0, r1, r2, r3, addr) \
    asm volatile("ldmatrix.sync.aligned.m8n8.x4.shared.b16 {%0,%1,%2,%3}, [%4];" \
                 : "=r"(r0), "=r"(r1), "=r"(r2), "=r"(r3) : "r"(addr))

#define MMA_BF16(c, a, b) \
    asm volatile("mma.sync.aligned.m16n8k16.row.col.f32.bf16.bf16.f32 " \
                 "{%0,%1,%2,%3}, {%4,%5,%6,%7}, {%8,%9}, {%0,%1,%2,%3};" \
                 : "+f"((c)[0]), "+f"((c)[1]), "+f"((c)[2]), "+f"((c)[3]) \
                 : "r"((a)[0]), "r"((a)[1]), "r"((a)[2]), "r"((a)[3]), \
                   "r"((b)[0]), "r"((b)[1]))

// ===================== conversion kernels =====================
__global__ void convA_kernel(const float4* __restrict__ pred) {
    int i = blockIdx.x * blockDim.x + threadIdx.x;      // B*D/4 = 1,048,576 float4s
    float4 v = pred[i];
    __nv_bfloat162 lo = __float22bfloat162_rn(make_float2(v.x, v.y));
    __nv_bfloat162 hi = __float22bfloat162_rn(make_float2(v.z, v.w));
    uint2 o;
    o.x = *reinterpret_cast<unsigned int*>(&lo);
    o.y = *reinterpret_cast<unsigned int*>(&hi);
    reinterpret_cast<uint2*>(g_predb)[i] = o;
}

__global__ void convB_kernel(const float* __restrict__ sig, int C) {
    __shared__ float tile[32][33];
    int c0 = blockIdx.x * 32, d0 = blockIdx.y * 32;
    int tx = threadIdx.x, ty = threadIdx.y;             // block (32, 8)
    #pragma unroll
    for (int i = 0; i < 4; i++) {
        int d = d0 + ty + i * 8, c = c0 + tx;
        tile[ty + i * 8][tx] = (c < C) ? sig[d * C + c] : 0.f;
    }
    __syncthreads();
    #pragma unroll
    for (int i = 0; i < 4; i++) {
        int c = c0 + ty + i * 8, d = d0 + tx;           // c < 2048 always valid (padded)
        g_sigT[c * D_SZ + d] = __float2bfloat16(tile[tx][ty + i * 8]);
    }
}

// ===================== gt: contiguous row dots =====================
__global__ void gt_kernel(const int* __restrict__ label) {
    int row = blockIdx.x * 8 + (threadIdx.x >> 5);
    int lane = threadIdx.x & 31;
    int lab = label[row];
    float4 a4 = reinterpret_cast<const float4*>(g_predb)[row * 32 + lane];
    float4 b4 = reinterpret_cast<const float4*>(g_sigT)[lab * 32 + lane];
    const __nv_bfloat162* ap = reinterpret_cast<const __nv_bfloat162*>(&a4);
    const __nv_bfloat162* bp = reinterpret_cast<const __nv_bfloat162*>(&b4);
    float s = 0.f;
    #pragma unroll
    for (int i = 0; i < 4; i++) {
        float2 fa = __bfloat1622float2(ap[i]);
        float2 fb = __bfloat1622float2(bp[i]);
        s += fa.x * fb.x + fa.y * fb.y;
    }
    #pragma unroll
    for (int o = 16; o > 0; o >>= 1) s += __shfl_down_sync(0xffffffffu, s, o);
    if (lane == 0) g_gt[row] = s;
}

// ===================== HMMA GEMM + hinge =====================
// CTA tile 128x128, 8 warps (warp tile 32x64), BK=64, double-buffered cp.async.
// SMEM stage: A 128 rows x 128B, B 128 rows x 128B (swizzled 16B segs).
#define STAGE_BYTES 16384
#define SMEM_B_OFF  32768
#define SMEM_TOTAL  65536

// swizzled offset within a stage: row r (0..127), 16B-segment seg (0..7)
__device__ __forceinline__ uint32_t swoff(int r, int seg) {
    return (uint32_t)(r * 128 + ((seg ^ (r & 7)) << 4));
}

__global__ void __launch_bounds__(256, 2)
gemm_hinge_kernel(const int* __restrict__ label, int C) {
    extern __shared__ char smem[];
    const uint32_t sb = smem_u32(smem);
    const int tid = threadIdx.x;
    const int wid = tid >> 5, lane = tid & 31;
    const int rowBase = blockIdx.y * 128;
    const int colBase = blockIdx.x * 128;

    // warp tile: 32 (M) x 64 (N)
    const int m0 = (wid & 3) * 32;
    const int n0 = (wid >> 2) * 64;

    // gmem load mapping: idx -> (row = idx>>3, seg = idx&7), 4 iters x 256 thr
    const __nv_bfloat16* Agm = g_predb + (size_t)rowBase * D_SZ;
    const __nv_bfloat16* Bgm = g_sigT + (size_t)colBase * D_SZ;

    float acc[2][8][4];
    #pragma unroll
    for (int i = 0; i < 2; i++)
        #pragma unroll
        for (int j = 0; j < 8; j++)
            #pragma unroll
            for (int q = 0; q < 4; q++) acc[i][j][q] = 0.f;

    // prefetch chunks 0,1
    #pragma unroll
    for (int st = 0; st < 2; st++) {
        #pragma unroll
        for (int it = 0; it < 4; it++) {
            int idx = it * 256 + tid;
            int r = idx >> 3, seg = idx & 7;
            CP_ASYNC16(sb + st * STAGE_BYTES + swoff(r, seg),
                       Agm + (size_t)r * D_SZ + st * 64 + seg * 8);
            CP_ASYNC16(sb + SMEM_B_OFF + st * STAGE_BYTES + swoff(r, seg),
                       Bgm + (size_t)r * D_SZ + st * 64 + seg * 8);
        }
        CP_COMMIT();
    }

    // ldmatrix per-lane address components
    const int rA = m0 + (lane & 15);           // + am*16
    const int rA7 = rA & 7;
    const int aSegHalf = (lane >> 4);          // 0/1 -> k half
    const int nB = n0 + ((lane >> 4) << 3) + (lane & 7);   // + bn*16
    const int nB7 = nB & 7;
    const int bSegHalf = (lane >> 3) & 1;

    for (int kc = 0; kc < 4; kc++) {
        CP_WAIT1();
        __syncthreads();
        const uint32_t Abase = sb + (kc & 1) * STAGE_BYTES;
        const uint32_t Bbase = sb + SMEM_B_OFF + (kc & 1) * STAGE_BYTES;

        #pragma unroll
        for (int s = 0; s < 4; s++) {
            uint32_t a[2][4];
            #pragma unroll
            for (int am = 0; am < 2; am++) {
                int r = rA + am * 16;
                uint32_t addr = Abase + r * 128 +
                                (((s * 2 + aSegHalf) ^ rA7) << 4);
                LDSM_X4(a[am][0], a[am][1], a[am][2], a[am][3], addr);
            }
            uint32_t b[8][2];
            #pragma unroll
            for (int bp = 0; bp < 4; bp++) {           // 2 n-atoms per ldmatrix.x4
                int n = nB + bp * 16;
                uint32_t addr = Bbase + n * 128 +
                                (((s * 2 + bSegHalf) ^ nB7) << 4);
                uint32_t r0, r1, r2, r3;
                LDSM_X4(r0, r1, r2, r3, addr);
                b[bp * 2][0] = r0; b[bp * 2][1] = r1;
                b[bp * 2 + 1][0] = r2; b[bp * 2 + 1][1] = r3;
            }
            #pragma unroll
            for (int am = 0; am < 2; am++)
                #pragma unroll
                for (int an = 0; an < 8; an++)
                    MMA_BF16(acc[am][an], a[am], b[an]);
        }
        __syncthreads();
        if (kc < 2) {
            int nc = kc + 2;
            #pragma unroll
            for (int it = 0; it < 4; it++) {
                int idx = it * 256 + tid;
                int r = idx >> 3, seg = idx & 7;
                CP_ASYNC16(sb + (kc & 1) * STAGE_BYTES + swoff(r, seg),
                           Agm + (size_t)r * D_SZ + nc * 64 + seg * 8);
                CP_ASYNC16(sb + SMEM_B_OFF + (kc & 1) * STAGE_BYTES + swoff(r, seg),
                           Bgm + (size_t)r * D_SZ + nc * 64 + seg * 8);
            }
        }
        CP_COMMIT();
    }

    // --- hinge epilogue ---
    // accum mapping (m16n8): c0,c1 -> row groupID, cols 2*tig, 2*tig+1
    //                        c2,c3 -> row groupID+8, same cols
    const int groupID = lane >> 2, tig = lane & 3;
    float lsum = 0.f;
    #pragma unroll
    for (int am = 0; am < 2; am++) {
        int r0g = rowBase + m0 + am * 16 + groupID;
        int r1g = r0g + 8;
        float gt0 = g_gt[r0g], gt1 = g_gt[r1g];
        int lab0 = label[r0g], lab1 = label[r1g];
        #pragma unroll
        for (int an = 0; an < 8; an++) {
            int c0 = colBase + n0 + an * 8 + 2 * tig;
            int c1 = c0 + 1;
            float* v = acc[am][an];
            if (c0 < C && c0 != lab0) lsum += fmaxf(1.0f + v[0] - gt0, 0.f);
            if (c1 < C && c1 != lab0) lsum += fmaxf(1.0f + v[1] - gt0, 0.f);
            if (c0 < C && c0 != lab1) lsum += fmaxf(1.0f + v[2] - gt1, 0.f);
            if (c1 < C && c1 != lab1) lsum += fmaxf(1.0f + v[3] - gt1, 0.f);
        }
    }

    // deterministic block tree reduction (reuse smem)
    float* red = reinterpret_cast<float*>(smem);
    __syncthreads();
    red[tid] = lsum;
    __syncthreads();
    #pragma unroll
    for (int st = 128; st > 0; st >>= 1) {
        if (tid < st) red[tid] += red[tid + st];
        __syncthreads();
    }
    if (tid == 0) g_partials[blockIdx.y * gridDim.x + blockIdx.x] = red[0];
}

// ===================== deterministic final reduction =====================
__global__ void final_reduce_kernel(float* __restrict__ out, int n) {
    __shared__ float s[256];
    float v = 0.f;
    for (int i = threadIdx.x; i < n; i += 256) v += g_partials[i];
    s[threadIdx.x] = v;
    __syncthreads();
    #pragma unroll
    for (int st = 128; st > 0; st >>= 1) {
        if (threadIdx.x < st) s[threadIdx.x] += s[threadIdx.x + st];
        __syncthreads();
    }
    if (threadIdx.x == 0) out[0] = s[0];
}

extern "C" void kernel_launch(void* const* d_in, const int* in_sizes, int n_in,
                              void* d_out, int out_size) {
    const float* pred  = (const float*)d_in[0];   // [B, D] fp32
    const int*   label = (const int*)d_in[1];     // [B] int32
    const float* sig   = (const float*)d_in[3];   // [D, C] fp32
    const int C = in_sizes[2];                    // 2000

    convA_kernel<<<4096, 256>>>(reinterpret_cast<const float4*>(pred));
    convB_kernel<<<dim3(64, 8), dim3(32, 8)>>>(sig, C);
    gt_kernel<<<B_SZ / 8, 256>>>(label);

    cudaFuncSetAttribute(gemm_hinge_kernel,
                         cudaFuncAttributeMaxDynamicSharedMemorySize, SMEM_TOTAL);
    dim3 grid(C_PAD / 128, B_SZ / 128);           // (16, 128) = 2048 CTAs
    gemm_hinge_kernel<<<grid, 256, SMEM_TOTAL>>>(label, C);

    final_reduce_kernel<<<1, 256>>>((float*)d_out, grid.x * grid.y);
}